// round 16
// baseline (speedup 1.0000x reference)
#include <cuda_runtime.h>
#include <math.h>

#define NN 50000
#define EE 800000
#define NT (EE + NN)   // edges + self loops = 850000
#define HC 128         // H*C
#define CC 64
#define NB 49          // scan blocks = ceil(NN/1024)
#define CB 3321        // count blocks = ceil(NT/256)
#define FB 3321        // fill blocks  = ceil(NT/256)
#define G1B 3125       // gemm1 blocks = NN/16

// ---------------- scratch (static device globals) --------------------------
__device__ __align__(16) float g_xl[NN * HC];
__device__ __align__(16) float g_xr[NN * HC];
__device__ __align__(16) float g_x [NN * CC];
__device__ int   g_rs  [NN];
__device__ int   g_deg [NN];    // zeroed by finalize for next replay (static-zero first run)
__device__ int   g_bsum[NB];
__device__ int   g_boff[NB];
__device__ int   g_scan_done;   // self-resetting
__device__ int   g_csr_src[NT];
__device__ float g_S1b[32][CC]; // replicated stat banks, self-resetting
__device__ float g_S2b[32][CC];
__device__ int   g_agg_done;    // self-resetting
__device__ __align__(16) float g_A[CC];
__device__ __align__(16) float g_B[CC];
// packed weights for layers 2,3: [layer][32 kpairs][64 colgroups][8 floats]
__device__ __align__(16) float g_Wp[2 * 32 * 64 * 8];

// ---------------- packed f32x2 helpers -------------------------------------
#define FMA2(acc, a, b) \
    asm("fma.rn.f32x2 %0, %1, %2, %0;" : "+l"(acc) : "l"(a), "l"(b))

__device__ __forceinline__ unsigned long long ADD2(unsigned long long a, unsigned long long b) {
    unsigned long long r;
    asm("add.rn.f32x2 %0, %1, %2;" : "=l"(r) : "l"(a), "l"(b));
    return r;
}
__device__ __forceinline__ unsigned long long MUL2(unsigned long long a, unsigned long long b) {
    unsigned long long r;
    asm("mul.rn.f32x2 %0, %1, %2;" : "=l"(r) : "l"(a), "l"(b));
    return r;
}
__device__ __forceinline__ float2 u2f(unsigned long long a) {
    float2 f;
    asm("mov.b64 {%0, %1}, %2;" : "=f"(f.x), "=f"(f.y) : "l"(a));
    return f;
}
__device__ __forceinline__ unsigned long long f2u(float x, float y) {
    unsigned long long r;
    asm("mov.b64 %0, {%1, %2};" : "=l"(r) : "f"(x), "f"(y));
    return r;
}
__device__ __forceinline__ float psum(unsigned long long a) {
    float2 f = u2f(a);
    return f.x + f.y;
}
__device__ __forceinline__ unsigned long long pmax(unsigned long long a, unsigned long long b) {
    float2 x = u2f(a), y = u2f(b);
    return f2u(fmaxf(x.x, y.x), fmaxf(x.y, y.y));
}

// ---------------- count (1 edge/thread) + wprep, fused by block range ------
__global__ void count_wprep_kernel(const int* __restrict__ ei,
                                   const float* __restrict__ Wl2, const float* __restrict__ Wr2,
                                   const float* __restrict__ Wl3, const float* __restrict__ Wr3) {
    if (blockIdx.x < CB) {
        int e = blockIdx.x * 256 + threadIdx.x;
        if (e < NT) {
            int d = (e < EE) ? ei[EE + e] : (e - EE);
            atomicAdd(&g_deg[d], 1);
        }
    } else {
        int idx = (blockIdx.x - CB) * 256 + threadIdx.x;  // 4096 total
        if (idx >= 2 * 2048) return;
        int L   = idx >> 11;
        int rem = idx & 2047;
        int kp  = rem >> 6;
        int cg  = rem & 63;
        const float* W = (cg < 32) ? (L ? Wl3 : Wl2) : (L ? Wr3 : Wr2);
        int c0 = (cg & 31) * 4;
        const float* r0 = W + (2 * kp) * HC + c0;
        const float* r1 = W + (2 * kp + 1) * HC + c0;
        float4 o0, o1;
        o0.x = r0[0]; o0.y = r1[0]; o0.z = r0[1]; o0.w = r1[1];
        o1.x = r0[2]; o1.y = r1[2]; o1.z = r0[3]; o1.w = r1[3];
        float4* dst = (float4*)(g_Wp + idx * 8);
        dst[0] = o0; dst[1] = o1;
    }
}

// per-block scan of deg -> g_rs (block-local exclusive) + g_bsum; the LAST
// block to finish also scans g_bsum -> g_boff.
__global__ void scanA_kernel() {
    __shared__ int wsum[32];
    __shared__ int lastflag;
    __shared__ int t0s;
    int tid = threadIdx.x, lane = tid & 31, wid = tid >> 5;
    int i = blockIdx.x * 1024 + tid;
    int v = (i < NN) ? g_deg[i] : 0;
    int x = v;
    #pragma unroll
    for (int o = 1; o < 32; o <<= 1) {
        int y = __shfl_up_sync(0xffffffffu, x, o);
        if (lane >= o) x += y;
    }
    if (lane == 31) wsum[wid] = x;
    __syncthreads();
    if (wid == 0) {
        int s = wsum[lane];
        #pragma unroll
        for (int o = 1; o < 32; o <<= 1) {
            int y = __shfl_up_sync(0xffffffffu, s, o);
            if (lane >= o) s += y;
        }
        wsum[lane] = s;
    }
    __syncthreads();
    int pre = wid ? wsum[wid - 1] : 0;
    if (i < NN) g_rs[i] = pre + x - v;
    if (tid == 1023) g_bsum[blockIdx.x] = pre + x;
    __syncthreads();
    if (tid == 0) {
        __threadfence();
        int t = atomicAdd(&g_scan_done, 1);
        lastflag = (t == (int)gridDim.x - 1) ? 1 : 0;
    }
    __syncthreads();
    if (lastflag) {
        int bv = 0, bx = 0;
        if (tid < 64) {
            bv = (tid < NB) ? g_bsum[tid] : 0;
            bx = bv;
            #pragma unroll
            for (int o = 1; o < 32; o <<= 1) {
                int y = __shfl_up_sync(0xffffffffu, bx, o);
                if (lane >= o) bx += y;
            }
        }
        if (tid == 31) t0s = bx;
        __syncthreads();
        if (tid >= 32 && tid < 64) bx += t0s;
        if (tid < NB) g_boff[tid] = bx - bv;
        if (tid == 0) g_scan_done = 0;
    }
}

// ---------------- fill (1 edge/thread) + gemm1 (din=3), fused --------------
__global__ void fill_gemm1_kernel(const int* __restrict__ ei,
                                  const float* __restrict__ xin,
                                  const float* __restrict__ Wl,
                                  const float* __restrict__ Wr) {
    if (blockIdx.x < FB) {
        int e = blockIdx.x * 256 + threadIdx.x;
        if (e < NT) {
            int s, d;
            if (e < EE) { s = ei[e]; d = ei[EE + e]; }
            else        { s = d = e - EE; }
            int pos = atomicAdd(&g_rs[d], 1) + g_boff[d >> 10];
            g_csr_src[pos] = s;
        }
    } else {
        __shared__ float sx[16][3];
        int base = (blockIdx.x - FB) * 16;
        if (threadIdx.x < 48) {
            int ln = threadIdx.x / 3, k = threadIdx.x % 3;
            sx[ln][k] = xin[(base + ln) * 3 + k];
        }
        __syncthreads();
        int cg = threadIdx.x & 63, nset = threadIdx.x >> 6;
        const float4* Wb; int c4;
        if (cg < 32) { Wb = (const float4*)Wl; c4 = cg; }
        else         { Wb = (const float4*)Wr; c4 = cg - 32; }
        float4 a[4];
        #pragma unroll
        for (int m = 0; m < 4; m++) a[m] = make_float4(0.f, 0.f, 0.f, 0.f);
        #pragma unroll
        for (int k = 0; k < 3; k++) {
            float4 w = Wb[k * 32 + c4];
            #pragma unroll
            for (int m = 0; m < 4; m++) {
                float xm = sx[nset + 4 * m][k];
                a[m].x = fmaf(xm, w.x, a[m].x);
                a[m].y = fmaf(xm, w.y, a[m].y);
                a[m].z = fmaf(xm, w.z, a[m].z);
                a[m].w = fmaf(xm, w.w, a[m].w);
            }
        }
        float* dst = (cg < 32) ? g_xl : g_xr;
        int c0 = c4 * 4;
        #pragma unroll
        for (int m = 0; m < 4; m++)
            *(float4*)(dst + (base + nset + 4 * m) * HC + c0) = a[m];
    }
}

// ---------------- layers 2,3 GEMM: packed f32x2, norm+relu fused ----------
__global__ void gemm2_kernel(int layer) {
    __shared__ float4 sxp4[256];   // = float2[16 nodes][32 kpairs]
    int base = blockIdx.x * 16;
    {
        int t = threadIdx.x;
        int n = t >> 4, q = t & 15;
        float4 v  = ((const float4*)g_x)[(base + n) * 16 + q];
        float4 A4 = ((const float4*)g_A)[q];
        float4 B4 = ((const float4*)g_B)[q];
        v.x = fmaxf(fmaf(A4.x, v.x, B4.x), 0.f);
        v.y = fmaxf(fmaf(A4.y, v.y, B4.y), 0.f);
        v.z = fmaxf(fmaf(A4.z, v.z, B4.z), 0.f);
        v.w = fmaxf(fmaf(A4.w, v.w, B4.w), 0.f);
        sxp4[n * 16 + q] = v;
    }
    __syncthreads();
    const float2* sxp2 = (const float2*)sxp4;   // [n*32 + kp]

    int cg   = threadIdx.x & 63;
    int nset = threadIdx.x >> 6;
    const ulonglong2* W2 = (const ulonglong2*)g_Wp + (size_t)layer * 4096 + cg * 2;

    unsigned long long acc[4][4];
    #pragma unroll
    for (int m = 0; m < 4; m++)
        #pragma unroll
        for (int j = 0; j < 4; j++) acc[m][j] = 0ull;

    #pragma unroll 8
    for (int kp = 0; kp < 32; kp++) {
        ulonglong2 wa = W2[kp * 128];
        ulonglong2 wb = W2[kp * 128 + 1];
        #pragma unroll
        for (int m = 0; m < 4; m++) {
            unsigned long long xd =
                *(const unsigned long long*)(sxp2 + (nset + 4 * m) * 32 + kp);
            FMA2(acc[m][0], xd, wa.x);
            FMA2(acc[m][1], xd, wa.y);
            FMA2(acc[m][2], xd, wb.x);
            FMA2(acc[m][3], xd, wb.y);
        }
    }
    float* dst = (cg < 32) ? g_xl : g_xr;
    int c0 = (cg & 31) * 4;
    #pragma unroll
    for (int m = 0; m < 4; m++) {
        float4 o;
        o.x = psum(acc[m][0]); o.y = psum(acc[m][1]);
        o.z = psum(acc[m][2]); o.w = psum(acc[m][3]);
        *(float4*)(dst + (base + nset + 4 * m) * HC + c0) = o;
    }
}

// ---------------- aggregation + fused GraphNorm statistics -----------------
// One warp per dst node, 4 warps/block. TWO edges per warp iteration:
//   slot = lane>>4 picks even/odd edge of the pair; j = lane&15 picks an
//   8-channel group (j<8: head0 ch j*8.., j>=8: head1). Logit reduction is
//   over 8 lanes (3 shfl.xor). Plain-exp softmax in exp2 domain; partial
//   z / weighted sums per slot are combined once at the end (exact).
__global__ void agg_kernel(const float* __restrict__ att,
                           const float* __restrict__ bias,
                           const float* __restrict__ gw,
                           const float* __restrict__ gb,
                           const float* __restrict__ gm) {
    __shared__ float sho[4][CC];
    __shared__ int lastflag;
    int w    = threadIdx.x >> 5;
    int n    = blockIdx.x * 4 + w;
    int lane = threadIdx.x & 31;
    int slot = lane >> 4;
    int j    = lane & 15;

    // per-lane 8 channels of xr and att (packed pairs)
    const float4* xrp = (const float4*)(g_xr + n * HC + j * 8);
    float4 xA = xrp[0], xB = xrp[1];
    unsigned long long xr0 = f2u(xA.x, xA.y), xr1 = f2u(xA.z, xA.w);
    unsigned long long xr2 = f2u(xB.x, xB.y), xr3 = f2u(xB.z, xB.w);
    const float LOG2E = 1.4426950408889634f;
    float4 aA = ((const float4*)att)[j * 2], aB = ((const float4*)att)[j * 2 + 1];
    unsigned long long a0 = f2u(aA.x * LOG2E, aA.y * LOG2E);
    unsigned long long a1 = f2u(aA.z * LOG2E, aA.w * LOG2E);
    unsigned long long a2 = f2u(aB.x * LOG2E, aB.y * LOG2E);
    unsigned long long a3 = f2u(aB.z * LOG2E, aB.w * LOG2E);
    const unsigned long long c02 = f2u(0.2f, 0.2f);

    int end = g_rs[n] + g_boff[n >> 10];
    int beg = end - g_deg[n];
    int iters = (end - beg + 1) >> 1;

    float z = 0.f;
    unsigned long long acc0 = 0ull, acc1 = 0ull, acc2 = 0ull, acc3 = 0ull;

    for (int t = 0; t < iters; t++) {
        int i = beg + 2 * t + slot;
        bool valid = i < end;
        int s = g_csr_src[valid ? i : beg];
        const ulonglong2* xlp = (const ulonglong2*)(g_xl + s * HC + j * 8);
        ulonglong2 r01 = xlp[0];
        ulonglong2 r23 = xlp[1];
        unsigned long long t0 = ADD2(r01.x, xr0);
        unsigned long long t1 = ADD2(r01.y, xr1);
        unsigned long long t2 = ADD2(r23.x, xr2);
        unsigned long long t3 = ADD2(r23.y, xr3);
        unsigned long long L0 = pmax(t0, MUL2(t0, c02));
        unsigned long long L1 = pmax(t1, MUL2(t1, c02));
        unsigned long long L2 = pmax(t2, MUL2(t2, c02));
        unsigned long long L3 = pmax(t3, MUL2(t3, c02));
        unsigned long long d = MUL2(L0, a0);
        FMA2(d, L1, a1);
        FMA2(d, L2, a2);
        FMA2(d, L3, a3);
        float p = psum(d);
        p += __shfl_xor_sync(0xffffffffu, p, 1);
        p += __shfl_xor_sync(0xffffffffu, p, 2);
        p += __shfl_xor_sync(0xffffffffu, p, 4);
        float wgt;
        asm("ex2.approx.ftz.f32 %0, %1;" : "=f"(wgt) : "f"(p));
        wgt = valid ? wgt : 0.f;
        z += wgt;
        unsigned long long wp = f2u(wgt, wgt);
        FMA2(acc0, wp, r01.x);
        FMA2(acc1, wp, r01.y);
        FMA2(acc2, wp, r23.x);
        FMA2(acc3, wp, r23.y);
    }

    // combine the two edge-slots (lane <-> lane^16: same channels, same head)
    z += __shfl_xor_sync(0xffffffffu, z, 16);
    float2 f0 = u2f(acc0), f1 = u2f(acc1), f2v = u2f(acc2), f3 = u2f(acc3);
    f0.x += __shfl_xor_sync(0xffffffffu, f0.x, 16);
    f0.y += __shfl_xor_sync(0xffffffffu, f0.y, 16);
    f1.x += __shfl_xor_sync(0xffffffffu, f1.x, 16);
    f1.y += __shfl_xor_sync(0xffffffffu, f1.y, 16);
    f2v.x += __shfl_xor_sync(0xffffffffu, f2v.x, 16);
    f2v.y += __shfl_xor_sync(0xffffffffu, f2v.y, 16);
    f3.x += __shfl_xor_sync(0xffffffffu, f3.x, 16);
    f3.y += __shfl_xor_sync(0xffffffffu, f3.y, 16);
    float inv = 1.f / z;   // per-head z (lane's head)
    f0.x *= inv; f0.y *= inv; f1.x *= inv; f1.y *= inv;
    f2v.x *= inv; f2v.y *= inv; f3.x *= inv; f3.y *= inv;

    // head mean: lane j (j<8, head0 ch j*8..) + lane j+8 (head1 same out ch)
    float h0 = __shfl_down_sync(0xffffffffu, f0.x, 8);
    float h1 = __shfl_down_sync(0xffffffffu, f0.y, 8);
    float h2 = __shfl_down_sync(0xffffffffu, f1.x, 8);
    float h3 = __shfl_down_sync(0xffffffffu, f1.y, 8);
    float h4 = __shfl_down_sync(0xffffffffu, f2v.x, 8);
    float h5 = __shfl_down_sync(0xffffffffu, f2v.y, 8);
    float h6 = __shfl_down_sync(0xffffffffu, f3.x, 8);
    float h7 = __shfl_down_sync(0xffffffffu, f3.y, 8);
    if (slot == 0 && j < 8) {
        float4 bA = ((const float4*)bias)[j * 2], bB = ((const float4*)bias)[j * 2 + 1];
        float4 oA, oB;
        oA.x = fmaf(0.5f, f0.x + h0, bA.x);
        oA.y = fmaf(0.5f, f0.y + h1, bA.y);
        oA.z = fmaf(0.5f, f1.x + h2, bA.z);
        oA.w = fmaf(0.5f, f1.y + h3, bA.w);
        oB.x = fmaf(0.5f, f2v.x + h4, bB.x);
        oB.y = fmaf(0.5f, f2v.y + h5, bB.y);
        oB.z = fmaf(0.5f, f3.x + h6, bB.z);
        oB.w = fmaf(0.5f, f3.y + h7, bB.w);
        float4* xo = (float4*)(g_x + n * CC + j * 8);
        xo[0] = oA; xo[1] = oB;
        float4* so = (float4*)(sho[w] + j * 8);
        so[0] = oA; so[1] = oB;
    }
    __syncthreads();

    // per-block stat reduction -> replicated banks
    if (threadIdx.x < CC) {
        int c = threadIdx.x;
        float s1 = 0.f, s2 = 0.f;
        #pragma unroll
        for (int r = 0; r < 4; r++) {
            float v = sho[r][c];
            s1 += v;
            s2 = fmaf(v, v, s2);
        }
        int bank = blockIdx.x & 31;
        atomicAdd(&g_S1b[bank][c], s1);
        atomicAdd(&g_S2b[bank][c], s2);
    }
    __syncthreads();
    if (threadIdx.x == 0) {
        __threadfence();
        int t = atomicAdd(&g_agg_done, 1);
        lastflag = (t == (int)gridDim.x - 1) ? 1 : 0;
    }
    __syncthreads();
    if (lastflag) {
        __threadfence();
        if (threadIdx.x < CC) {
            int c = threadIdx.x;
            float S1 = 0.f, S2 = 0.f;
            #pragma unroll
            for (int b = 0; b < 32; b++) {
                S1 += g_S1b[b][c];
                S2 += g_S2b[b][c];
                g_S1b[b][c] = 0.f;     // reset for next layer / next replay
                g_S2b[b][c] = 0.f;
            }
            const float invN = 1.f / (float)NN;
            float mu  = S1 * invN;
            float gmv = gm[c];
            float var = S2 * invN - (2.f * gmv - gmv * gmv) * mu * mu;
            float A = gw[c] * rsqrtf(var + 1e-5f);
            g_A[c] = A;
            g_B[c] = gb[c] - A * gmv * mu;
        }
        if (threadIdx.x == 0) g_agg_done = 0;
    }
}

// ---------------- final norm + relu (also resets g_deg for next replay) ----
__global__ void finalize_kernel(float* __restrict__ out) {
    int i = blockIdx.x * blockDim.x + threadIdx.x;   // NN*16 float4s
    if (i < NN) g_deg[i] = 0;
    if (i >= NN * 16) return;
    int q = i & 15;
    float4 v  = ((const float4*)g_x)[i];
    float4 A4 = ((const float4*)g_A)[q];
    float4 B4 = ((const float4*)g_B)[q];
    float4 o;
    o.x = fmaxf(fmaf(A4.x, v.x, B4.x), 0.f);
    o.y = fmaxf(fmaf(A4.y, v.y, B4.y), 0.f);
    o.z = fmaxf(fmaf(A4.z, v.z, B4.z), 0.f);
    o.w = fmaxf(fmaf(A4.w, v.w, B4.w), 0.f);
    ((float4*)out)[i] = o;
}

// ---------------- launch ----------------------------------------------------
extern "C" void kernel_launch(void* const* d_in, const int* in_sizes, int n_in,
                              void* d_out, int out_size) {
    (void)in_sizes; (void)n_in; (void)out_size;
    const float* x  = (const float*)d_in[0];
    const int*   ei = (const int*)d_in[1];
    const float* P[21];
    for (int i = 0; i < 21; i++) P[i] = (const float*)d_in[2 + i];
    // per-layer params at P[l*7 + {Wl,Wr,att,b,gw,gb,gm}]

    count_wprep_kernel<<<CB + 16, 256>>>(ei, P[7], P[8], P[14], P[15]);
    scanA_kernel<<<NB, 1024>>>();                       // includes bsum scan
    fill_gemm1_kernel<<<FB + G1B, 256>>>(ei, x, P[0], P[1]);

    // layer 1
    agg_kernel  <<<NN / 4, 128>>>(P[2], P[3], P[4], P[5], P[6]);

    // layer 2
    gemm2_kernel<<<NN / 16, 256>>>(0);
    agg_kernel  <<<NN / 4, 128>>>(P[9], P[10], P[11], P[12], P[13]);

    // layer 3
    gemm2_kernel<<<NN / 16, 256>>>(1);
    agg_kernel  <<<NN / 4, 128>>>(P[16], P[17], P[18], P[19], P[20]);

    finalize_kernel<<<(NN * 16 + 255) / 256, 256>>>((float*)d_out);
}